// round 1
// baseline (speedup 1.0000x reference)
#include <cuda_runtime.h>
#include <math.h>

#define B_      2
#define S_      2048
#define HIDDEN_ 4096
#define HD_     128
#define HQ_     32
#define HKV_    8
#define WINDOW_ 1024
#define CAP_    50.0f
#define EPS_    1e-5f

#define M_ROWS  (B_ * S_)   // 4096

// ---------------- scratch (static device globals; no allocation) ----------------
__device__ float g_xn[(size_t)M_ROWS * HIDDEN_];
__device__ float g_q [(size_t)M_ROWS * HQ_  * HD_];
__device__ float g_k [(size_t)M_ROWS * HKV_ * HD_];
__device__ float g_v [(size_t)M_ROWS * HKV_ * HD_];
__device__ float g_ao[(size_t)M_ROWS * HQ_  * HD_];

// ---------------- RMSNorm: one block per row ----------------
__global__ void rmsnorm_kernel(const float* __restrict__ x,
                               const float* __restrict__ gamma,
                               float* __restrict__ xn) {
    int row = blockIdx.x;
    const float4* xr  = (const float4*)(x  + (size_t)row * HIDDEN_);
    float4*       xnr = (float4*)      (xn + (size_t)row * HIDDEN_);
    const float4* g4  = (const float4*)gamma;
    int t = threadIdx.x;

    float ss = 0.f;
    float4 vals[4];
#pragma unroll
    for (int i = 0; i < 4; i++) {
        float4 v = xr[t + i * 256];
        vals[i] = v;
        ss += v.x * v.x + v.y * v.y + v.z * v.z + v.w * v.w;
    }
    __shared__ float red[256];
    red[t] = ss;
    __syncthreads();
    for (int s = 128; s > 0; s >>= 1) {
        if (t < s) red[t] += red[t + s];
        __syncthreads();
    }
    float rms = rsqrtf(red[0] / (float)HIDDEN_ + EPS_);
#pragma unroll
    for (int i = 0; i < 4; i++) {
        float4 v = vals[i];
        float4 g = g4[t + i * 256];
        float4 o;
        o.x = v.x * rms * g.x;
        o.y = v.y * rms * g.y;
        o.z = v.z * rms * g.z;
        o.w = v.w * rms * g.w;
        xnr[t + i * 256] = o;
    }
}

// ---------------- SGEMM: C[M,N] = A[M,K] @ B[K,N] (+ resid), row-major ----------------
#define GBM 128
#define GBN 128
#define GBK 8

__global__ void __launch_bounds__(256)
sgemm_kernel(const float* __restrict__ A, const float* __restrict__ Bw,
             const float* __restrict__ resid, float* __restrict__ C,
             int N, int K) {
    __shared__ float As[GBK][GBM];
    __shared__ float Bs[GBK][GBN];

    int tid = threadIdx.x;
    int tx = tid & 15;
    int ty = tid >> 4;

    const float* Ab = A  + (size_t)blockIdx.y * GBM * K;
    const float* Bb = Bw + (size_t)blockIdx.x * GBN;

    int arow = tid >> 1;
    int acol = (tid & 1) * 4;
    int brow = tid >> 5;
    int bcol = (tid & 31) * 4;

    float acc[8][8];
#pragma unroll
    for (int i = 0; i < 8; i++)
#pragma unroll
        for (int j = 0; j < 8; j++) acc[i][j] = 0.f;

    for (int k0 = 0; k0 < K; k0 += GBK) {
        float4 av = *(const float4*)(Ab + (size_t)arow * K + k0 + acol);
        As[acol + 0][arow] = av.x;
        As[acol + 1][arow] = av.y;
        As[acol + 2][arow] = av.z;
        As[acol + 3][arow] = av.w;
        *(float4*)&Bs[brow][bcol] = *(const float4*)(Bb + (size_t)(k0 + brow) * N + bcol);
        __syncthreads();
#pragma unroll
        for (int kk = 0; kk < GBK; kk++) {
            float a[8], b[8];
            *(float4*)(a)     = *(float4*)&As[kk][ty * 8];
            *(float4*)(a + 4) = *(float4*)&As[kk][ty * 8 + 4];
            *(float4*)(b)     = *(float4*)&Bs[kk][tx * 8];
            *(float4*)(b + 4) = *(float4*)&Bs[kk][tx * 8 + 4];
#pragma unroll
            for (int i = 0; i < 8; i++)
#pragma unroll
                for (int j = 0; j < 8; j++)
                    acc[i][j] += a[i] * b[j];
        }
        __syncthreads();
    }

#pragma unroll
    for (int i = 0; i < 8; i++) {
        size_t row = (size_t)blockIdx.y * GBM + ty * 8 + i;
        float* crow = C + row * N + blockIdx.x * GBN + tx * 8;
        float4 o0 = make_float4(acc[i][0], acc[i][1], acc[i][2], acc[i][3]);
        float4 o1 = make_float4(acc[i][4], acc[i][5], acc[i][6], acc[i][7]);
        if (resid) {
            const float* rrow = resid + row * N + blockIdx.x * GBN + tx * 8;
            float4 r0 = *(const float4*)rrow;
            float4 r1 = *(const float4*)(rrow + 4);
            o0.x += r0.x; o0.y += r0.y; o0.z += r0.z; o0.w += r0.w;
            o1.x += r1.x; o1.y += r1.y; o1.z += r1.z; o1.w += r1.w;
        }
        *(float4*)(crow)     = o0;
        *(float4*)(crow + 4) = o1;
    }
}

// ---------------- RoPE (in place), t shaped [B,S,n_heads,HD] ----------------
__global__ void rope_kernel(float* __restrict__ t, int n_heads, int total) {
    int idx = blockIdx.x * blockDim.x + threadIdx.x;
    if (idx >= total) return;
    int d   = idx & 63;
    int h   = (idx >> 6) % n_heads;
    int row = idx / (64 * n_heads);     // b*S + s
    int s   = row % S_;

    float inv = expf(-((float)(2 * d) / (float)HD_) * logf(10000.0f));
    float ang = (float)s * inv;
    float c, sn;
    sincosf(ang, &sn, &c);

    float* base = t + ((size_t)row * n_heads + h) * HD_;
    float v1 = base[d];
    float v2 = base[d + 64];
    base[d]      = v1 * c - v2 * sn;
    base[d + 64] = v2 * c + v1 * sn;
}

// ---------------- windowed causal attention with tanh cap ----------------
// grid: (S/AQ, HQ, B); block = 512 threads (16 warps), one query per warp.
// K/V tiles of 32 keys staged in smem, shared by all 16 queries.
#define AQ 16
#define AT 32

__global__ void __launch_bounds__(512)
attn_kernel(const float* __restrict__ q, const float* __restrict__ k,
            const float* __restrict__ v, float* __restrict__ o) {
    __shared__ float Ks[AT][HD_];
    __shared__ float Vs[AT][HD_];

    int warp = threadIdx.x >> 5;
    int lane = threadIdx.x & 31;
    int i0 = blockIdx.x * AQ;
    int h  = blockIdx.y;
    int b  = blockIdx.z;
    int g  = h >> 2;            // HQ/HKV = 4
    int i  = i0 + warp;

    const float* qp = q + (((size_t)b * S_ + i) * HQ_ + h) * HD_;
    float4 qv = *(const float4*)(qp + lane * 4);

    float m = -INFINITY, lsum = 0.f;
    float4 acc = make_float4(0.f, 0.f, 0.f, 0.f);

    int jstart = max(0, i0 - (WINDOW_ - 1));
    int t0_beg = jstart & ~(AT - 1);
    int jend   = i0 + AQ - 1;

    int lrow = threadIdx.x >> 4;        // 0..31
    int lcol = (threadIdx.x & 15) * 8;  // 0..120

    const float scale = 0.08838834764831845f;  // 1/sqrt(128)

    for (int t0 = t0_beg; t0 <= jend; t0 += AT) {
        int j = t0 + lrow;
        const float* kp = k + (((size_t)b * S_ + j) * HKV_ + g) * HD_ + lcol;
        const float* vp = v + (((size_t)b * S_ + j) * HKV_ + g) * HD_ + lcol;
        *(float4*)&Ks[lrow][lcol]     = *(const float4*)(kp);
        *(float4*)&Ks[lrow][lcol + 4] = *(const float4*)(kp + 4);
        *(float4*)&Vs[lrow][lcol]     = *(const float4*)(vp);
        *(float4*)&Vs[lrow][lcol + 4] = *(const float4*)(vp + 4);
        __syncthreads();

        if (t0 <= i) {
            int jjend = min(AT - 1, i - t0);
            int jjbeg = max(0, (i - (WINDOW_ - 1)) - t0);
            for (int jj = jjbeg; jj <= jjend; jj++) {
                float4 kv = *(float4*)&Ks[jj][lane * 4];
                float s = qv.x * kv.x + qv.y * kv.y + qv.z * kv.z + qv.w * kv.w;
#pragma unroll
                for (int off = 16; off > 0; off >>= 1)
                    s += __shfl_xor_sync(0xffffffffu, s, off);
                s *= scale;
                // s = CAP * tanh(s / CAP) via exp: tanh(x) = (1 - e^-2x)/(1 + e^-2x)
                float e2 = __expf(s * (-2.0f / CAP_));
                s = CAP_ * (1.f - e2) / (1.f + e2);

                if (s > m) {
                    float cfac = __expf(m - s);
                    m = s;
                    lsum *= cfac;
                    acc.x *= cfac; acc.y *= cfac; acc.z *= cfac; acc.w *= cfac;
                }
                float p = __expf(s - m);
                lsum += p;
                float4 vv = *(float4*)&Vs[jj][lane * 4];
                acc.x += p * vv.x; acc.y += p * vv.y;
                acc.z += p * vv.z; acc.w += p * vv.w;
            }
        }
        __syncthreads();
    }

    float invl = 1.0f / lsum;
    float4 out = make_float4(acc.x * invl, acc.y * invl, acc.z * invl, acc.w * invl);
    float* op = o + (((size_t)b * S_ + i) * HQ_ + h) * HD_ + lane * 4;
    *(float4*)op = out;
}

// ---------------- launch ----------------
extern "C" void kernel_launch(void* const* d_in, const int* in_sizes, int n_in,
                              void* d_out, int out_size) {
    const float* x     = (const float*)d_in[0];
    const float* gamma = (const float*)d_in[1];
    const float* Wq    = (const float*)d_in[2];
    const float* Wk    = (const float*)d_in[3];
    const float* Wv    = (const float*)d_in[4];
    const float* Wo    = (const float*)d_in[5];
    float* out = (float*)d_out;

    float *xn, *qb, *kb, *vb, *ao;
    cudaGetSymbolAddress((void**)&xn, g_xn);
    cudaGetSymbolAddress((void**)&qb, g_q);
    cudaGetSymbolAddress((void**)&kb, g_k);
    cudaGetSymbolAddress((void**)&vb, g_v);
    cudaGetSymbolAddress((void**)&ao, g_ao);

    // 1) RMSNorm
    rmsnorm_kernel<<<M_ROWS, 256>>>(x, gamma, xn);

    // 2) Q/K/V projections
    dim3 gq(HQ_ * HD_ / GBN, M_ROWS / GBM);    // (32, 32)
    sgemm_kernel<<<gq, 256>>>(xn, Wq, nullptr, qb, HQ_ * HD_, HIDDEN_);
    dim3 gk(HKV_ * HD_ / GBN, M_ROWS / GBM);   // (8, 32)
    sgemm_kernel<<<gk, 256>>>(xn, Wk, nullptr, kb, HKV_ * HD_, HIDDEN_);
    sgemm_kernel<<<gk, 256>>>(xn, Wv, nullptr, vb, HKV_ * HD_, HIDDEN_);

    // 3) RoPE on q and k
    int tot_q = B_ * S_ * HQ_ * (HD_ / 2);
    rope_kernel<<<(tot_q + 255) / 256, 256>>>(qb, HQ_, tot_q);
    int tot_k = B_ * S_ * HKV_ * (HD_ / 2);
    rope_kernel<<<(tot_k + 255) / 256, 256>>>(kb, HKV_, tot_k);

    // 4) attention
    dim3 ga(S_ / AQ, HQ_, B_);                 // (128, 32, 2)
    attn_kernel<<<ga, 512>>>(qb, kb, vb, ao);

    // 5) output projection + residual
    dim3 go(HIDDEN_ / GBN, M_ROWS / GBM);      // (32, 32)
    sgemm_kernel<<<go, 256>>>(ao, Wo, x, out, HIDDEN_, HQ_ * HD_);
}

// round 2
// speedup vs baseline: 1.3446x; 1.3446x over previous
#include <cuda_runtime.h>
#include <math.h>

#define B_      2
#define S_      2048
#define HIDDEN_ 4096
#define HD_     128
#define HQ_     32
#define HKV_    8
#define WINDOW_ 1024
#define CAP_    50.0f
#define EPS_    1e-5f

#define M_ROWS  (B_ * S_)   // 4096

// ---------------- scratch (static device globals; no allocation) ----------------
__device__ float g_xn[(size_t)M_ROWS * HIDDEN_];
__device__ float g_q [(size_t)M_ROWS * HQ_  * HD_];
__device__ float g_k [(size_t)M_ROWS * HKV_ * HD_];
__device__ float g_v [(size_t)M_ROWS * HKV_ * HD_];
__device__ float g_ao[(size_t)M_ROWS * HQ_  * HD_];

// ---------------- RMSNorm: one block per row ----------------
__global__ void rmsnorm_kernel(const float* __restrict__ x,
                               const float* __restrict__ gamma,
                               float* __restrict__ xn) {
    int row = blockIdx.x;
    const float4* xr  = (const float4*)(x  + (size_t)row * HIDDEN_);
    float4*       xnr = (float4*)      (xn + (size_t)row * HIDDEN_);
    const float4* g4  = (const float4*)gamma;
    int t = threadIdx.x;

    float ss = 0.f;
    float4 vals[4];
#pragma unroll
    for (int i = 0; i < 4; i++) {
        float4 v = xr[t + i * 256];
        vals[i] = v;
        ss += v.x * v.x + v.y * v.y + v.z * v.z + v.w * v.w;
    }
    __shared__ float red[256];
    red[t] = ss;
    __syncthreads();
    for (int s = 128; s > 0; s >>= 1) {
        if (t < s) red[t] += red[t + s];
        __syncthreads();
    }
    float rms = rsqrtf(red[0] / (float)HIDDEN_ + EPS_);
#pragma unroll
    for (int i = 0; i < 4; i++) {
        float4 v = vals[i];
        float4 g = g4[t + i * 256];
        float4 o;
        o.x = v.x * rms * g.x;
        o.y = v.y * rms * g.y;
        o.z = v.z * rms * g.z;
        o.w = v.w * rms * g.w;
        xnr[t + i * 256] = o;
    }
}

// ---------------- SGEMM: C[M,N] = A[M,K] @ B[K,N] (+ resid), row-major ----------------
#define GBM 128
#define GBN 128
#define GBK 8

__global__ void __launch_bounds__(256)
sgemm_kernel(const float* __restrict__ A, const float* __restrict__ Bw,
             const float* __restrict__ resid, float* __restrict__ C,
             int N, int K) {
    __shared__ float As[GBK][GBM];
    __shared__ float Bs[GBK][GBN];

    int tid = threadIdx.x;
    int tx = tid & 15;
    int ty = tid >> 4;

    const float* Ab = A  + (size_t)blockIdx.y * GBM * K;
    const float* Bb = Bw + (size_t)blockIdx.x * GBN;

    int arow = tid >> 1;
    int acol = (tid & 1) * 4;
    int brow = tid >> 5;
    int bcol = (tid & 31) * 4;

    float acc[8][8];
#pragma unroll
    for (int i = 0; i < 8; i++)
#pragma unroll
        for (int j = 0; j < 8; j++) acc[i][j] = 0.f;

    for (int k0 = 0; k0 < K; k0 += GBK) {
        float4 av = *(const float4*)(Ab + (size_t)arow * K + k0 + acol);
        As[acol + 0][arow] = av.x;
        As[acol + 1][arow] = av.y;
        As[acol + 2][arow] = av.z;
        As[acol + 3][arow] = av.w;
        *(float4*)&Bs[brow][bcol] = *(const float4*)(Bb + (size_t)(k0 + brow) * N + bcol);
        __syncthreads();
#pragma unroll
        for (int kk = 0; kk < GBK; kk++) {
            float a[8], b[8];
            *(float4*)(a)     = *(float4*)&As[kk][ty * 8];
            *(float4*)(a + 4) = *(float4*)&As[kk][ty * 8 + 4];
            *(float4*)(b)     = *(float4*)&Bs[kk][tx * 8];
            *(float4*)(b + 4) = *(float4*)&Bs[kk][tx * 8 + 4];
#pragma unroll
            for (int i = 0; i < 8; i++)
#pragma unroll
                for (int j = 0; j < 8; j++)
                    acc[i][j] += a[i] * b[j];
        }
        __syncthreads();
    }

#pragma unroll
    for (int i = 0; i < 8; i++) {
        size_t row = (size_t)blockIdx.y * GBM + ty * 8 + i;
        float* crow = C + row * N + blockIdx.x * GBN + tx * 8;
        float4 o0 = make_float4(acc[i][0], acc[i][1], acc[i][2], acc[i][3]);
        float4 o1 = make_float4(acc[i][4], acc[i][5], acc[i][6], acc[i][7]);
        if (resid) {
            const float* rrow = resid + row * N + blockIdx.x * GBN + tx * 8;
            float4 r0 = *(const float4*)rrow;
            float4 r1 = *(const float4*)(rrow + 4);
            o0.x += r0.x; o0.y += r0.y; o0.z += r0.z; o0.w += r0.w;
            o1.x += r1.x; o1.y += r1.y; o1.z += r1.z; o1.w += r1.w;
        }
        *(float4*)(crow)     = o0;
        *(float4*)(crow + 4) = o1;
    }
}

// ---------------- RoPE (in place), t shaped [B,S,n_heads,HD] ----------------
__global__ void rope_kernel(float* __restrict__ t, int n_heads, int total) {
    int idx = blockIdx.x * blockDim.x + threadIdx.x;
    if (idx >= total) return;
    int d   = idx & 63;
    int h   = (idx >> 6) % n_heads;
    int row = idx / (64 * n_heads);     // b*S + s
    int s   = row % S_;

    float inv = expf(-((float)(2 * d) / (float)HD_) * logf(10000.0f));
    float ang = (float)s * inv;
    float c, sn;
    sincosf(ang, &sn, &c);

    float* base = t + ((size_t)row * n_heads + h) * HD_;
    float v1 = base[d];
    float v2 = base[d + 64];
    base[d]      = v1 * c - v2 * sn;
    base[d + 64] = v2 * c + v1 * sn;
}

// ---------------- windowed causal attention, lane-per-key flash style ----------------
// Block: 512 threads = 16 warps. Each warp owns 4 consecutive queries (AQW).
// Block covers AQB = 64 queries of one (b, h). K/V tiles of AT=32 keys in smem.
// Lane j of a warp computes scores for key t0+j against all 4 of its queries.
#define NW    16
#define AQW   4
#define AQB   (NW * AQW)     // 64
#define AT    32
#define KPAD  132            // 128 + 4 floats pad: conflict-free float4 rows

#define ATTN_SMEM_FLOATS (2 * AT * KPAD + AQB * HD_ + NW * AT * 8)
#define ATTN_SMEM_BYTES  (ATTN_SMEM_FLOATS * 4)   // 82944

__global__ void __launch_bounds__(512, 2)
attn_kernel(const float* __restrict__ q, const float* __restrict__ k,
            const float* __restrict__ v, float* __restrict__ o) {
    extern __shared__ float sm[];
    float* Ks = sm;                       // [AT][KPAD]
    float* Vs = Ks + AT * KPAD;           // [AT][KPAD]
    float* Qs = Vs + AT * KPAD;           // [AQB][HD_]
    float* Ps = Qs + AQB * HD_;           // [NW][AT][8]

    int tid  = threadIdx.x;
    int warp = tid >> 5;
    int lane = tid & 31;
    int i0 = blockIdx.x * AQB;
    int h  = blockIdx.y;
    int b  = blockIdx.z;
    int g  = h >> 2;                      // HQ/HKV = 4
    int iw0 = i0 + warp * AQW;

    // stage Q tile: 64 rows x 128 floats
    {
        int r = tid >> 3;                 // 0..63
        int c = (tid & 7) * 16;           // 0..112
        const float4* src = (const float4*)(q + (((size_t)b * S_ + (i0 + r)) * HQ_ + h) * HD_ + c);
        float4* dst = (float4*)&Qs[r * HD_ + c];
#pragma unroll
        for (int u = 0; u < 4; u++) dst[u] = src[u];
    }

    float m[AQW], l[AQW];
    float4 acc[AQW];
#pragma unroll
    for (int qq = 0; qq < AQW; qq++) {
        m[qq] = -1e30f; l[qq] = 0.f;
        acc[qq] = make_float4(0.f, 0.f, 0.f, 0.f);
    }

    int jstart = max(0, i0 - (WINDOW_ - 1)) & ~(AT - 1);
    int jend   = i0 + AQB - 1;

    int lrow = tid >> 4;                  // 0..31
    int lcol = (tid & 15) * 8;            // 0..120

    const float scale = 0.08838834764831845f;   // 1/sqrt(128)
    float* pw = &Ps[warp * AT * 8];

    for (int t0 = jstart; t0 <= jend; t0 += AT) {
        // stage K/V tile (32 rows x 128 floats each)
        {
            int j = t0 + lrow;
            const float* kp = k + (((size_t)b * S_ + j) * HKV_ + g) * HD_ + lcol;
            const float* vp = v + (((size_t)b * S_ + j) * HKV_ + g) * HD_ + lcol;
            *(float4*)&Ks[lrow * KPAD + lcol]     = ((const float4*)kp)[0];
            *(float4*)&Ks[lrow * KPAD + lcol + 4] = ((const float4*)kp)[1];
            *(float4*)&Vs[lrow * KPAD + lcol]     = ((const float4*)vp)[0];
            *(float4*)&Vs[lrow * KPAD + lcol + 4] = ((const float4*)vp)[1];
        }
        __syncthreads();

        if (t0 <= iw0 + AQW - 1) {
            // ---- scores: lane = key t0+lane, 4 queries per warp ----
            float s[AQW] = {0.f, 0.f, 0.f, 0.f};
            const float* krow = &Ks[lane * KPAD];
            const float* qbase = &Qs[warp * AQW * HD_];
#pragma unroll 8
            for (int d4 = 0; d4 < 32; d4++) {
                float4 kv = *(const float4*)(krow + d4 * 4);
#pragma unroll
                for (int qq = 0; qq < AQW; qq++) {
                    float4 qv = *(const float4*)(qbase + qq * HD_ + d4 * 4);
                    s[qq] += qv.x * kv.x + qv.y * kv.y + qv.z * kv.z + qv.w * kv.w;
                }
            }

            int j = t0 + lane;
#pragma unroll
            for (int qq = 0; qq < AQW; qq++) {
                int i = iw0 + qq;
                float sv = s[qq] * scale;
                // cap: CAP*tanh(sv/CAP) via exp
                float e2 = __expf(sv * (-2.0f / CAP_));
                sv = CAP_ * __fdividef(1.f - e2, 1.f + e2);
                bool valid = (j <= i) && (j > i - WINDOW_);
                sv = valid ? sv : -1e30f;

                // warp max
                float tm = sv;
#pragma unroll
                for (int off = 16; off > 0; off >>= 1)
                    tm = fmaxf(tm, __shfl_xor_sync(0xffffffffu, tm, off));
                float mn = fmaxf(m[qq], tm);
                float corr = __expf(m[qq] - mn);
                m[qq] = mn;
                float p = __expf(sv - mn);
                float psum = p;
#pragma unroll
                for (int off = 16; off > 0; off >>= 1)
                    psum += __shfl_xor_sync(0xffffffffu, psum, off);
                l[qq] = l[qq] * corr + psum;
                acc[qq].x *= corr; acc[qq].y *= corr;
                acc[qq].z *= corr; acc[qq].w *= corr;
                pw[lane * 8 + qq] = p;
            }
            __syncwarp();

            // ---- PV: lane owns out dims [lane*4, lane*4+4) ----
#pragma unroll 4
            for (int jj = 0; jj < AT; jj++) {
                float4 pv = *(const float4*)(pw + jj * 8);           // broadcast
                float4 vv = *(const float4*)&Vs[jj * KPAD + lane * 4];
                acc[0].x += pv.x * vv.x; acc[0].y += pv.x * vv.y;
                acc[0].z += pv.x * vv.z; acc[0].w += pv.x * vv.w;
                acc[1].x += pv.y * vv.x; acc[1].y += pv.y * vv.y;
                acc[1].z += pv.y * vv.z; acc[1].w += pv.y * vv.w;
                acc[2].x += pv.z * vv.x; acc[2].y += pv.z * vv.y;
                acc[2].z += pv.z * vv.z; acc[2].w += pv.z * vv.w;
                acc[3].x += pv.w * vv.x; acc[3].y += pv.w * vv.y;
                acc[3].z += pv.w * vv.z; acc[3].w += pv.w * vv.w;
            }
        }
        __syncthreads();
    }

#pragma unroll
    for (int qq = 0; qq < AQW; qq++) {
        int i = iw0 + qq;
        float inv = 1.0f / l[qq];
        float4 o4 = make_float4(acc[qq].x * inv, acc[qq].y * inv,
                                acc[qq].z * inv, acc[qq].w * inv);
        *(float4*)(o + (((size_t)b * S_ + i) * HQ_ + h) * HD_ + lane * 4) = o4;
    }
}

// ---------------- launch ----------------
extern "C" void kernel_launch(void* const* d_in, const int* in_sizes, int n_in,
                              void* d_out, int out_size) {
    const float* x     = (const float*)d_in[0];
    const float* gamma = (const float*)d_in[1];
    const float* Wq    = (const float*)d_in[2];
    const float* Wk    = (const float*)d_in[3];
    const float* Wv    = (const float*)d_in[4];
    const float* Wo    = (const float*)d_in[5];
    float* out = (float*)d_out;

    float *xn, *qb, *kb, *vb, *ao;
    cudaGetSymbolAddress((void**)&xn, g_xn);
    cudaGetSymbolAddress((void**)&qb, g_q);
    cudaGetSymbolAddress((void**)&kb, g_k);
    cudaGetSymbolAddress((void**)&vb, g_v);
    cudaGetSymbolAddress((void**)&ao, g_ao);

    cudaFuncSetAttribute(attn_kernel,
                         cudaFuncAttributeMaxDynamicSharedMemorySize,
                         ATTN_SMEM_BYTES);

    // 1) RMSNorm
    rmsnorm_kernel<<<M_ROWS, 256>>>(x, gamma, xn);

    // 2) Q/K/V projections
    dim3 gq(HQ_ * HD_ / GBN, M_ROWS / GBM);    // (32, 32)
    sgemm_kernel<<<gq, 256>>>(xn, Wq, nullptr, qb, HQ_ * HD_, HIDDEN_);
    dim3 gk(HKV_ * HD_ / GBN, M_ROWS / GBM);   // (8, 32)
    sgemm_kernel<<<gk, 256>>>(xn, Wk, nullptr, kb, HKV_ * HD_, HIDDEN_);
    sgemm_kernel<<<gk, 256>>>(xn, Wv, nullptr, vb, HKV_ * HD_, HIDDEN_);

    // 3) RoPE on q and k
    int tot_q = B_ * S_ * HQ_ * (HD_ / 2);
    rope_kernel<<<(tot_q + 255) / 256, 256>>>(qb, HQ_, tot_q);
    int tot_k = B_ * S_ * HKV_ * (HD_ / 2);
    rope_kernel<<<(tot_k + 255) / 256, 256>>>(kb, HKV_, tot_k);

    // 4) attention
    dim3 ga(S_ / AQB, HQ_, B_);                // (32, 32, 2)
    attn_kernel<<<ga, 512, ATTN_SMEM_BYTES>>>(qb, kb, vb, ao);

    // 5) output projection + residual
    dim3 go(HIDDEN_ / GBN, M_ROWS / GBM);      // (32, 32)
    sgemm_kernel<<<go, 256>>>(ao, Wo, x, out, HIDDEN_, HQ_ * HD_);
}

// round 3
// speedup vs baseline: 2.7598x; 2.0525x over previous
#include <cuda_runtime.h>
#include <math.h>
#include <stdint.h>

#define B_      2
#define S_      2048
#define HIDDEN_ 4096
#define HD_     128
#define HQ_     32
#define HKV_    8
#define WINDOW_ 1024
#define CAP_    50.0f
#define EPS_    1e-5f

#define M_ROWS  (B_ * S_)   // 4096

// ---------------- scratch (static device globals; no allocation) ----------------
__device__ float g_xn[(size_t)M_ROWS * HIDDEN_];
__device__ float g_q [(size_t)M_ROWS * HQ_  * HD_];
__device__ float g_k [(size_t)M_ROWS * HKV_ * HD_];
__device__ float g_v [(size_t)M_ROWS * HKV_ * HD_];
__device__ float g_ao[(size_t)M_ROWS * HQ_  * HD_];

// ---------------- RMSNorm: one block per row ----------------
__global__ void rmsnorm_kernel(const float* __restrict__ x,
                               const float* __restrict__ gamma,
                               float* __restrict__ xn) {
    int row = blockIdx.x;
    const float4* xr  = (const float4*)(x  + (size_t)row * HIDDEN_);
    float4*       xnr = (float4*)      (xn + (size_t)row * HIDDEN_);
    const float4* g4  = (const float4*)gamma;
    int t = threadIdx.x;

    float ss = 0.f;
    float4 vals[4];
#pragma unroll
    for (int i = 0; i < 4; i++) {
        float4 v = xr[t + i * 256];
        vals[i] = v;
        ss += v.x * v.x + v.y * v.y + v.z * v.z + v.w * v.w;
    }
    __shared__ float red[256];
    red[t] = ss;
    __syncthreads();
    for (int s = 128; s > 0; s >>= 1) {
        if (t < s) red[t] += red[t + s];
        __syncthreads();
    }
    float rms = rsqrtf(red[0] / (float)HIDDEN_ + EPS_);
#pragma unroll
    for (int i = 0; i < 4; i++) {
        float4 v = vals[i];
        float4 g = g4[t + i * 256];
        float4 o;
        o.x = v.x * rms * g.x;
        o.y = v.y * rms * g.y;
        o.z = v.z * rms * g.z;
        o.w = v.w * rms * g.w;
        xnr[t + i * 256] = o;
    }
}

// ---------------- TF32 tensor-core GEMM ----------------
// C[M,N] = A[M,K] @ B[K,N] (+resid). Block tile 128x128x16, 256 threads,
// warp grid 2(m) x 4(n), warp tile 64x32 via mma.m16n8k8 tf32.
#define TBM 128
#define TBN 128
#define TBK 16
#define APAD 20    // A smem row stride (floats): conflict-free frag loads
#define BPAD 132   // B smem row stride

__device__ __forceinline__ uint32_t f2tf32(float f) {
    uint32_t r;
    asm("cvt.rna.tf32.f32 %0, %1;" : "=r"(r) : "f"(f));
    return r;
}

__global__ void __launch_bounds__(256, 2)
tf32_gemm_kernel(const float* __restrict__ A, const float* __restrict__ Bw,
                 const float* __restrict__ resid, float* __restrict__ C,
                 int N, int K) {
    __shared__ uint32_t As[TBM * APAD];   // [m][k] pad
    __shared__ uint32_t Bs[TBK * BPAD];   // [k][n] pad

    int tid  = threadIdx.x;
    int warp = tid >> 5;
    int lane = tid & 31;
    int gid  = lane >> 2;       // 0..7
    int l4   = lane & 3;        // 0..3
    int wm = (warp & 1) * 64;   // warp m offset in tile
    int wn = (warp >> 1) * 32;  // warp n offset in tile

    size_t bm0 = (size_t)blockIdx.y * TBM;
    int    bn0 = blockIdx.x * TBN;

    const float* Ab = A  + bm0 * K;
    const float* Bb = Bw + bn0;

    float acc[4][4][4];
#pragma unroll
    for (int mt = 0; mt < 4; mt++)
#pragma unroll
        for (int nt = 0; nt < 4; nt++)
#pragma unroll
            for (int r = 0; r < 4; r++) acc[mt][nt][r] = 0.f;

    for (int k0 = 0; k0 < K; k0 += TBK) {
        // stage A tile: 128 rows x 16 cols = 512 float4
#pragma unroll
        for (int i = 0; i < 2; i++) {
            int j = tid + i * 256;
            int row = j >> 2;
            int c4  = j & 3;
            float4 v = *(const float4*)(Ab + (size_t)row * K + k0 + c4 * 4);
            uint32_t* d = &As[row * APAD + c4 * 4];
            d[0] = f2tf32(v.x); d[1] = f2tf32(v.y);
            d[2] = f2tf32(v.z); d[3] = f2tf32(v.w);
        }
        // stage B tile: 16 rows x 128 cols = 512 float4
#pragma unroll
        for (int i = 0; i < 2; i++) {
            int j = tid + i * 256;
            int row = j >> 5;
            int c4  = j & 31;
            float4 v = *(const float4*)(Bb + (size_t)(k0 + row) * N + c4 * 4);
            uint32_t* d = &Bs[row * BPAD + c4 * 4];
            d[0] = f2tf32(v.x); d[1] = f2tf32(v.y);
            d[2] = f2tf32(v.z); d[3] = f2tf32(v.w);
        }
        __syncthreads();

#pragma unroll
        for (int kk = 0; kk < TBK; kk += 8) {
            uint32_t a[4][4], b[4][2];
#pragma unroll
            for (int mt = 0; mt < 4; mt++) {
                int ab = (wm + mt * 16 + gid) * APAD + kk + l4;
                a[mt][0] = As[ab];
                a[mt][1] = As[ab + 8 * APAD];
                a[mt][2] = As[ab + 4];
                a[mt][3] = As[ab + 8 * APAD + 4];
            }
#pragma unroll
            for (int nt = 0; nt < 4; nt++) {
                int bb = (kk + l4) * BPAD + wn + nt * 8 + gid;
                b[nt][0] = Bs[bb];
                b[nt][1] = Bs[bb + 4 * BPAD];
            }
#pragma unroll
            for (int mt = 0; mt < 4; mt++)
#pragma unroll
                for (int nt = 0; nt < 4; nt++) {
                    asm volatile(
                        "mma.sync.aligned.m16n8k8.row.col.f32.tf32.tf32.f32 "
                        "{%0,%1,%2,%3}, {%4,%5,%6,%7}, {%8,%9}, {%0,%1,%2,%3};"
                        : "+f"(acc[mt][nt][0]), "+f"(acc[mt][nt][1]),
                          "+f"(acc[mt][nt][2]), "+f"(acc[mt][nt][3])
                        : "r"(a[mt][0]), "r"(a[mt][1]), "r"(a[mt][2]), "r"(a[mt][3]),
                          "r"(b[nt][0]), "r"(b[nt][1]));
                }
        }
        __syncthreads();
    }

    // epilogue
#pragma unroll
    for (int mt = 0; mt < 4; mt++) {
#pragma unroll
        for (int nt = 0; nt < 4; nt++) {
            int row = wm + mt * 16 + gid;
            int col = wn + nt * 8 + l4 * 2;
            size_t g0 = (bm0 + row) * N + bn0 + col;
            size_t g1 = g0 + (size_t)8 * N;
            float2 v0 = make_float2(acc[mt][nt][0], acc[mt][nt][1]);
            float2 v1 = make_float2(acc[mt][nt][2], acc[mt][nt][3]);
            if (resid) {
                float2 r0 = *(const float2*)(resid + g0);
                float2 r1 = *(const float2*)(resid + g1);
                v0.x += r0.x; v0.y += r0.y;
                v1.x += r1.x; v1.y += r1.y;
            }
            *(float2*)(C + g0) = v0;
            *(float2*)(C + g1) = v1;
        }
    }
}

// ---------------- RoPE (in place), t shaped [B,S,n_heads,HD] ----------------
__global__ void rope_kernel(float* __restrict__ t, int n_heads, int total) {
    int idx = blockIdx.x * blockDim.x + threadIdx.x;
    if (idx >= total) return;
    int d   = idx & 63;
    int h   = (idx >> 6) % n_heads;
    int row = idx / (64 * n_heads);     // b*S + s
    int s   = row % S_;

    float inv = expf(-((float)(2 * d) / (float)HD_) * logf(10000.0f));
    float ang = (float)s * inv;
    float c, sn;
    sincosf(ang, &sn, &c);

    float* base = t + ((size_t)row * n_heads + h) * HD_;
    float v1 = base[d];
    float v2 = base[d + 64];
    base[d]      = v1 * c - v2 * sn;
    base[d + 64] = v2 * c + v1 * sn;
}

// ---------------- windowed causal attention, lane-per-key flash style ----------------
#define NW    16
#define AQW   4
#define AQB   (NW * AQW)     // 64
#define AT    32
#define KPAD  132            // 128 + 4 floats pad

#define ATTN_SMEM_FLOATS (2 * AT * KPAD + AQB * HD_ + NW * AT * 8)
#define ATTN_SMEM_BYTES  (ATTN_SMEM_FLOATS * 4)   // 82944

__global__ void __launch_bounds__(512, 2)
attn_kernel(const float* __restrict__ q, const float* __restrict__ k,
            const float* __restrict__ v, float* __restrict__ o) {
    extern __shared__ float sm[];
    float* Ks = sm;                       // [AT][KPAD]
    float* Vs = Ks + AT * KPAD;           // [AT][KPAD]
    float* Qs = Vs + AT * KPAD;           // [AQB][HD_]
    float* Ps = Qs + AQB * HD_;           // [NW][AT][8]

    int tid  = threadIdx.x;
    int warp = tid >> 5;
    int lane = tid & 31;
    int i0 = blockIdx.x * AQB;
    int h  = blockIdx.y;
    int b  = blockIdx.z;
    int g  = h >> 2;                      // HQ/HKV = 4
    int iw0 = i0 + warp * AQW;

    // stage Q tile: 64 rows x 128 floats
    {
        int r = tid >> 3;                 // 0..63
        int c = (tid & 7) * 16;           // 0..112
        const float4* src = (const float4*)(q + (((size_t)b * S_ + (i0 + r)) * HQ_ + h) * HD_ + c);
        float4* dst = (float4*)&Qs[r * HD_ + c];
#pragma unroll
        for (int u = 0; u < 4; u++) dst[u] = src[u];
    }

    float m[AQW], l[AQW];
    float4 acc[AQW];
#pragma unroll
    for (int qq = 0; qq < AQW; qq++) {
        m[qq] = -1e30f; l[qq] = 0.f;
        acc[qq] = make_float4(0.f, 0.f, 0.f, 0.f);
    }

    int jstart = max(0, i0 - (WINDOW_ - 1)) & ~(AT - 1);
    int jend   = i0 + AQB - 1;

    int lrow = tid >> 4;                  // 0..31
    int lcol = (tid & 15) * 8;            // 0..120

    const float scale = 0.08838834764831845f;   // 1/sqrt(128)
    float* pw = &Ps[warp * AT * 8];

    for (int t0 = jstart; t0 <= jend; t0 += AT) {
        {
            int j = t0 + lrow;
            const float* kp = k + (((size_t)b * S_ + j) * HKV_ + g) * HD_ + lcol;
            const float* vp = v + (((size_t)b * S_ + j) * HKV_ + g) * HD_ + lcol;
            *(float4*)&Ks[lrow * KPAD + lcol]     = ((const float4*)kp)[0];
            *(float4*)&Ks[lrow * KPAD + lcol + 4] = ((const float4*)kp)[1];
            *(float4*)&Vs[lrow * KPAD + lcol]     = ((const float4*)vp)[0];
            *(float4*)&Vs[lrow * KPAD + lcol + 4] = ((const float4*)vp)[1];
        }
        __syncthreads();

        if (t0 <= iw0 + AQW - 1) {
            float s[AQW] = {0.f, 0.f, 0.f, 0.f};
            const float* krow = &Ks[lane * KPAD];
            const float* qbase = &Qs[warp * AQW * HD_];
#pragma unroll 8
            for (int d4 = 0; d4 < 32; d4++) {
                float4 kv = *(const float4*)(krow + d4 * 4);
#pragma unroll
                for (int qq = 0; qq < AQW; qq++) {
                    float4 qv = *(const float4*)(qbase + qq * HD_ + d4 * 4);
                    s[qq] += qv.x * kv.x + qv.y * kv.y + qv.z * kv.z + qv.w * kv.w;
                }
            }

            int j = t0 + lane;
#pragma unroll
            for (int qq = 0; qq < AQW; qq++) {
                int i = iw0 + qq;
                float sv = s[qq] * scale;
                float e2 = __expf(sv * (-2.0f / CAP_));
                sv = CAP_ * __fdividef(1.f - e2, 1.f + e2);
                bool valid = (j <= i) && (j > i - WINDOW_);
                sv = valid ? sv : -1e30f;

                float tm = sv;
#pragma unroll
                for (int off = 16; off > 0; off >>= 1)
                    tm = fmaxf(tm, __shfl_xor_sync(0xffffffffu, tm, off));
                float mn = fmaxf(m[qq], tm);
                float corr = __expf(m[qq] - mn);
                m[qq] = mn;
                float p = __expf(sv - mn);
                float psum = p;
#pragma unroll
                for (int off = 16; off > 0; off >>= 1)
                    psum += __shfl_xor_sync(0xffffffffu, psum, off);
                l[qq] = l[qq] * corr + psum;
                acc[qq].x *= corr; acc[qq].y *= corr;
                acc[qq].z *= corr; acc[qq].w *= corr;
                pw[lane * 8 + qq] = p;
            }
            __syncwarp();

#pragma unroll 4
            for (int jj = 0; jj < AT; jj++) {
                float4 pv = *(const float4*)(pw + jj * 8);
                float4 vv = *(const float4*)&Vs[jj * KPAD + lane * 4];
                acc[0].x += pv.x * vv.x; acc[0].y += pv.x * vv.y;
                acc[0].z += pv.x * vv.z; acc[0].w += pv.x * vv.w;
                acc[1].x += pv.y * vv.x; acc[1].y += pv.y * vv.y;
                acc[1].z += pv.y * vv.z; acc[1].w += pv.y * vv.w;
                acc[2].x += pv.z * vv.x; acc[2].y += pv.z * vv.y;
                acc[2].z += pv.z * vv.z; acc[2].w += pv.z * vv.w;
                acc[3].x += pv.w * vv.x; acc[3].y += pv.w * vv.y;
                acc[3].z += pv.w * vv.z; acc[3].w += pv.w * vv.w;
            }
        }
        __syncthreads();
    }

#pragma unroll
    for (int qq = 0; qq < AQW; qq++) {
        int i = iw0 + qq;
        float inv = 1.0f / l[qq];
        float4 o4 = make_float4(acc[qq].x * inv, acc[qq].y * inv,
                                acc[qq].z * inv, acc[qq].w * inv);
        *(float4*)(o + (((size_t)b * S_ + i) * HQ_ + h) * HD_ + lane * 4) = o4;
    }
}

// ---------------- launch ----------------
extern "C" void kernel_launch(void* const* d_in, const int* in_sizes, int n_in,
                              void* d_out, int out_size) {
    const float* x     = (const float*)d_in[0];
    const float* gamma = (const float*)d_in[1];
    const float* Wq    = (const float*)d_in[2];
    const float* Wk    = (const float*)d_in[3];
    const float* Wv    = (const float*)d_in[4];
    const float* Wo    = (const float*)d_in[5];
    float* out = (float*)d_out;

    float *xn, *qb, *kb, *vb, *ao;
    cudaGetSymbolAddress((void**)&xn, g_xn);
    cudaGetSymbolAddress((void**)&qb, g_q);
    cudaGetSymbolAddress((void**)&kb, g_k);
    cudaGetSymbolAddress((void**)&vb, g_v);
    cudaGetSymbolAddress((void**)&ao, g_ao);

    cudaFuncSetAttribute(attn_kernel,
                         cudaFuncAttributeMaxDynamicSharedMemorySize,
                         ATTN_SMEM_BYTES);

    // 1) RMSNorm
    rmsnorm_kernel<<<M_ROWS, 256>>>(x, gamma, xn);

    // 2) Q/K/V projections (tf32 tensor cores)
    dim3 gq(HQ_ * HD_ / TBN, M_ROWS / TBM);    // (32, 32)
    tf32_gemm_kernel<<<gq, 256>>>(xn, Wq, nullptr, qb, HQ_ * HD_, HIDDEN_);
    dim3 gk(HKV_ * HD_ / TBN, M_ROWS / TBM);   // (8, 32)
    tf32_gemm_kernel<<<gk, 256>>>(xn, Wk, nullptr, kb, HKV_ * HD_, HIDDEN_);
    tf32_gemm_kernel<<<gk, 256>>>(xn, Wv, nullptr, vb, HKV_ * HD_, HIDDEN_);

    // 3) RoPE on q and k
    int tot_q = B_ * S_ * HQ_ * (HD_ / 2);
    rope_kernel<<<(tot_q + 255) / 256, 256>>>(qb, HQ_, tot_q);
    int tot_k = B_ * S_ * HKV_ * (HD_ / 2);
    rope_kernel<<<(tot_k + 255) / 256, 256>>>(kb, HKV_, tot_k);

    // 4) attention
    dim3 ga(S_ / AQB, HQ_, B_);                // (32, 32, 2)
    attn_kernel<<<ga, 512, ATTN_SMEM_BYTES>>>(qb, kb, vb, ao);

    // 5) output projection + residual (tf32 tensor cores)
    dim3 go(HIDDEN_ / TBN, M_ROWS / TBM);      // (32, 32)
    tf32_gemm_kernel<<<go, 256>>>(ao, Wo, x, out, HIDDEN_, HQ_ * HD_);
}